// round 10
// baseline (speedup 1.0000x reference)
#include <cuda_runtime.h>
#include <cuda_bf16.h>
#include <cstdint>

#define F_DIM   132
#define M_TOTAL 24
#define D_IN    136
#define BM      256
#define NT      512
#define KSB     272                 // row stride bytes = 136 bf16, 16B-aligned, conflict-free
#define B_ROWS  136

#define A_BYTES (BM * KSB)          // 69632
#define B_BYTES (B_ROWS * KSB)      // 36992
#define SM_BIAS 0                   // 136 floats
#define SM_AH   1024
#define SM_AL   (SM_AH + A_BYTES)   // 70656
#define SM_BH   (SM_AL + A_BYTES)   // 140288
#define SM_BL   (SM_BH + B_BYTES)   // 177280
#define SM_TOTAL (SM_BL + B_BYTES)  // 214272
#define MCH     (16 * KSB)          // m/n 16-row chunk stride = 4352

typedef unsigned int u32;

__device__ __forceinline__ u32 smem_u32(const void* p) {
    u32 a;
    asm("{ .reg .u64 t; cvta.to.shared.u64 t, %1; cvt.u32.u64 %0, t; }"
        : "=r"(a) : "l"(p));
    return a;
}

__device__ __forceinline__ void ldmat4(u32* r, u32 addr) {
    asm volatile("ldmatrix.sync.aligned.m8n8.x4.shared.b16 {%0,%1,%2,%3}, [%4];"
        : "=r"(r[0]), "=r"(r[1]), "=r"(r[2]), "=r"(r[3]) : "r"(addr));
}
__device__ __forceinline__ void ldmat2(u32* r, u32 addr) {
    asm volatile("ldmatrix.sync.aligned.m8n8.x2.shared.b16 {%0,%1}, [%2];"
        : "=r"(r[0]), "=r"(r[1]) : "r"(addr));
}
__device__ __forceinline__ void ldmat1(u32* r, u32 addr) {
    asm volatile("ldmatrix.sync.aligned.m8n8.x1.shared.b16 {%0}, [%1];"
        : "=r"(r[0]) : "r"(addr));
}
__device__ __forceinline__ void mma_bf16(float* c, const u32* a, const u32* b) {
    asm volatile("mma.sync.aligned.m16n8k16.row.col.f32.bf16.bf16.f32 "
        "{%0,%1,%2,%3}, {%4,%5,%6,%7}, {%8,%9}, {%0,%1,%2,%3};"
        : "+f"(c[0]), "+f"(c[1]), "+f"(c[2]), "+f"(c[3])
        : "r"(a[0]), "r"(a[1]), "r"(a[2]), "r"(a[3]), "r"(b[0]), "r"(b[1]));
}
__device__ __forceinline__ void mma_bf16_k8(float* c, const u32* a, u32 b) {
    asm volatile("mma.sync.aligned.m16n8k8.row.col.f32.bf16.bf16.f32 "
        "{%0,%1,%2,%3}, {%4,%5}, {%6}, {%0,%1,%2,%3};"
        : "+f"(c[0]), "+f"(c[1]), "+f"(c[2]), "+f"(c[3])
        : "r"(a[0]), "r"(a[1]), "r"(b));
}

// bf16 hi/lo split of two fp32 values; hi/lo packed bf16x2 (first value -> low half)
__device__ __forceinline__ void split2(float a, float b, u32& hi, u32& lo) {
    __nv_bfloat16 ha = __float2bfloat16(a);
    __nv_bfloat16 hb = __float2bfloat16(b);
    __nv_bfloat16 la = __float2bfloat16(a - __bfloat162float(ha));
    __nv_bfloat16 lb = __float2bfloat16(b - __bfloat162float(hb));
    hi = ((u32)__bfloat16_as_ushort(hb) << 16) | (u32)__bfloat16_as_ushort(ha);
    lo = ((u32)__bfloat16_as_ushort(lb) << 16) | (u32)__bfloat16_as_ushort(la);
}

__global__ __launch_bounds__(NT, 1)
void exchange_mma2_kernel(const float* __restrict__ x,
                          const float* __restrict__ ev,
                          const float* __restrict__ W,
                          const float* __restrict__ b,
                          float* __restrict__ out,
                          int n, int numTiles)
{
    extern __shared__ char smem[];
    const u32 sb = smem_u32(smem);
    const int tid  = threadIdx.x;
    const int lane = tid & 31;
    const int wid  = tid >> 5;
    const int mg   = wid & 7;       // m-group: rows mg*32 .. mg*32+31
    const int ng   = wid >> 3;      // n-group: cols ng*64 .. (+64 or +72)
    float* bs = (float*)(smem + SM_BIAS);
    float* out2base = out + (size_t)n * F_DIM;

    // ---- one-time: bias + Bh/Bl = bf16 hi/lo of W^T (Bs[nn][kk] = W[kk][nn]) ----
    for (int i = tid; i < D_IN; i += NT)
        bs[i] = b[i];
    for (int idx = tid; idx < D_IN * D_IN; idx += NT) {
        int kk = idx / D_IN;
        int nn = idx % D_IN;
        float wv = W[idx];
        __nv_bfloat16 h = __float2bfloat16(wv);
        __nv_bfloat16 l = __float2bfloat16(wv - __bfloat162float(h));
        *(__nv_bfloat16*)(smem + SM_BH + nn * KSB + kk * 2) = h;
        *(__nv_bfloat16*)(smem + SM_BL + nn * KSB + kk * 2) = l;
    }

    // ---- per-lane fragment addresses ----
    const u32 aRow = (u32)((lane & 7) + ((lane >> 3) & 1) * 8);
    const u32 aK   = (u32)(((lane >> 4) & 1) * 16);
    const u32 aAddr  = sb + SM_AH + (mg * 32 + aRow) * KSB + aK;
    const u32 aAddr8 = sb + SM_AH + (mg * 32 + (lane & 15)) * KSB + 256;   // k8 tail
    const u32 bRow = (u32)((lane & 7) + ((lane >> 4) & 1) * 8);
    const u32 bK   = (u32)(((lane >> 3) & 1) * 16);
    const u32 bAddr  = sb + SM_BH + (ng * 64 + bRow) * KSB + bK;
    const u32 bAddr8 = sb + SM_BH + (ng * 64 + (lane & 15)) * KSB + 256;
    const u32 bAddrE  = sb + SM_BH + (128 + (lane & 7)) * KSB + bK;        // cols 128..135
    const u32 bAddrE8 = sb + SM_BH + (128 + (lane & 7)) * KSB + 256;

    const int r = tid >> 1;     // staging row within tile (0..255)
    const int h = tid & 1;      // staging half

    for (int tile = blockIdx.x; tile < numTiles; tile += gridDim.x) {
        const int rowBase = tile * BM;
        __syncthreads();   // previous tile's compute done before restaging A

        // ================= stage A tile (2 threads per row) =================
        {
            const int row = rowBase + r;
            const bool valid = row < n;
            const float4* xrow = (const float4*)(x + (size_t)row * F_DIM);
            const float4 zf4 = make_float4(0.f, 0.f, 0.f, 0.f);
            float4 xr[17];
            float c0 = 0.f, c1 = 0.f, c2 = 0.f, c3 = 0.f;

            if (h == 0) {
                #pragma unroll
                for (int i = 0; i < 8; i++) {
                    xr[2 * i]     = valid ? xrow[4 * i]     : zf4;
                    xr[2 * i + 1] = valid ? xrow[4 * i + 1] : zf4;
                }
                xr[16] = valid ? xrow[32] : zf4;
                if (valid) {
                    const float4* er = (const float4*)(ev + (size_t)row * M_TOTAL);
                    float e[24];
                    #pragma unroll
                    for (int i = 0; i < 6; i++) {
                        float4 v = er[i];
                        e[4 * i] = v.x; e[4 * i + 1] = v.y;
                        e[4 * i + 2] = v.z; e[4 * i + 3] = v.w;
                    }
                    #pragma unroll
                    for (int m = 0;  m < 3;  m++) c0 += e[m] * e[m];
                    #pragma unroll
                    for (int m = 3;  m < 8;  m++) c1 += e[m] * e[m];
                    #pragma unroll
                    for (int m = 8;  m < 15; m++) c2 += e[m] * e[m];
                    #pragma unroll
                    for (int m = 15; m < 24; m++) c3 += e[m] * e[m];
                }
            } else {
                #pragma unroll
                for (int i = 0; i < 8; i++) {
                    xr[2 * i]     = valid ? xrow[4 * i + 2] : zf4;
                    xr[2 * i + 1] = valid ? xrow[4 * i + 3] : zf4;
                }
            }

            char* Ah = smem + SM_AH + r * KSB;
            char* Al = smem + SM_AL + r * KSB;
            #pragma unroll
            for (int i = 0; i < 8; i++) {
                int c = 2 * i + h;
                uint4 hi, lo;
                split2(xr[2 * i].x,     xr[2 * i].y,     hi.x, lo.x);
                split2(xr[2 * i].z,     xr[2 * i].w,     hi.y, lo.y);
                split2(xr[2 * i + 1].x, xr[2 * i + 1].y, hi.z, lo.z);
                split2(xr[2 * i + 1].z, xr[2 * i + 1].w, hi.w, lo.w);
                *(uint4*)(Ah + c * 16) = hi;
                *(uint4*)(Al + c * 16) = lo;
            }
            if (h == 0) {      // chunk 16 (k128..135): x[128..131] + contr[132..135]
                uint4 hi, lo;
                split2(xr[16].x, xr[16].y, hi.x, lo.x);
                split2(xr[16].z, xr[16].w, hi.y, lo.y);
                split2(c0, c1, hi.z, lo.z);
                split2(c2, c3, hi.w, lo.w);
                *(uint4*)(Ah + 256) = hi;
                *(uint4*)(Al + 256) = lo;
            }
        }
        __syncthreads();

        // ================= compute: warp tile m32 x n64(+8) =================
        float acc[2][9][4];
        #pragma unroll
        for (int m = 0; m < 2; m++)
            #pragma unroll
            for (int j = 0; j < 9; j++)
                #pragma unroll
                for (int q = 0; q < 4; q++)
                    acc[m][j][q] = 0.f;

        #pragma unroll 1
        for (int s = 0; s < 8; s++) {           // k16 steps, k = s*16
            u32 ah[2][4], al[2][4];
            #pragma unroll
            for (int m = 0; m < 2; m++) {
                ldmat4(ah[m], aAddr + (u32)(m * MCH + s * 32));
                ldmat4(al[m], aAddr + (u32)(m * MCH + s * 32) + (SM_AL - SM_AH));
            }
            #pragma unroll
            for (int j = 0; j < 4; j++) {       // n16 chunks
                u32 bh[4], bl[4];
                u32 ba = bAddr + (u32)(j * MCH + s * 32);
                ldmat4(bh, ba);
                ldmat4(bl, ba + B_BYTES);
                #pragma unroll
                for (int m = 0; m < 2; m++) {
                    mma_bf16(acc[m][2 * j],     ah[m], bh);
                    mma_bf16(acc[m][2 * j + 1], ah[m], bh + 2);
                    mma_bf16(acc[m][2 * j],     ah[m], bl);
                    mma_bf16(acc[m][2 * j + 1], ah[m], bl + 2);
                    mma_bf16(acc[m][2 * j],     al[m], bh);
                    mma_bf16(acc[m][2 * j + 1], al[m], bh + 2);
                }
            }
            if (ng == 1) {                      // extra n8 chunk: cols 128..135
                u32 bh2[2], bl2[2];
                ldmat2(bh2, bAddrE + (u32)(s * 32));
                ldmat2(bl2, bAddrE + (u32)(s * 32) + B_BYTES);
                #pragma unroll
                for (int m = 0; m < 2; m++) {
                    mma_bf16(acc[m][8], ah[m], bh2);
                    mma_bf16(acc[m][8], ah[m], bl2);
                    mma_bf16(acc[m][8], al[m], bh2);
                }
            }
        }
        {   // ---- k8 tail: k = 128..135 ----
            u32 a2h[2][2], a2l[2][2];
            #pragma unroll
            for (int m = 0; m < 2; m++) {
                ldmat2(a2h[m], aAddr8 + (u32)(m * MCH));
                ldmat2(a2l[m], aAddr8 + (u32)(m * MCH) + (SM_AL - SM_AH));
            }
            #pragma unroll
            for (int j = 0; j < 4; j++) {
                u32 b2h[2], b2l[2];
                u32 ba = bAddr8 + (u32)(j * MCH);
                ldmat2(b2h, ba);
                ldmat2(b2l, ba + B_BYTES);
                #pragma unroll
                for (int m = 0; m < 2; m++)
                    #pragma unroll
                    for (int hf = 0; hf < 2; hf++) {
                        mma_bf16_k8(acc[m][2 * j + hf], a2h[m], b2h[hf]);
                        mma_bf16_k8(acc[m][2 * j + hf], a2h[m], b2l[hf]);
                        mma_bf16_k8(acc[m][2 * j + hf], a2l[m], b2h[hf]);
                    }
            }
            if (ng == 1) {
                u32 b1h[1], b1l[1];
                ldmat1(b1h, bAddrE8);
                ldmat1(b1l, bAddrE8 + B_BYTES);
                #pragma unroll
                for (int m = 0; m < 2; m++) {
                    mma_bf16_k8(acc[m][8], a2h[m], b1h[0]);
                    mma_bf16_k8(acc[m][8], a2h[m], b1l[0]);
                    mma_bf16_k8(acc[m][8], a2l[m], b1h[0]);
                }
            }
        }

        // ================= epilogue: direct fragment stores =================
        const int cp = lane & 3;
        #pragma unroll
        for (int m = 0; m < 2; m++) {
            const int r0 = rowBase + mg * 32 + m * 16 + (lane >> 2);
            const int r1 = r0 + 8;
            #pragma unroll
            for (int j = 0; j < 9; j++) {
                if (j == 8 && ng == 0) continue;
                int col = ng * 64 + j * 8 + cp * 2;
                if (col < F_DIM) {
                    float b0 = bs[col], b1 = bs[col + 1];
                    if (r0 < n)
                        *(float2*)(out + (size_t)r0 * F_DIM + col) =
                            make_float2(acc[m][j][0] + b0, acc[m][j][1] + b1);
                    if (r1 < n)
                        *(float2*)(out + (size_t)r1 * F_DIM + col) =
                            make_float2(acc[m][j][2] + b0, acc[m][j][3] + b1);
                }
            }
        }

        // cols 132..135 gate ev -> out2 (ng==1, chunk j=8, cp in {2,3})
        if (ng == 1) {
            int col = 128 + cp * 2;
            float gb0 = (cp >= 2) ? bs[col]     : 0.f;
            float gb1 = (cp >= 2) ? bs[col + 1] : 0.f;
            #pragma unroll
            for (int m = 0; m < 2; m++) {
                const int r0 = rowBase + mg * 32 + m * 16 + (lane >> 2);
                const int r1 = r0 + 8;
                float o0 = acc[m][8][0] + gb0, o1 = acc[m][8][1] + gb1;
                float o2 = acc[m][8][2] + gb0, o3 = acc[m][8][3] + gb1;
                float p0 = __shfl_xor_sync(0xffffffffu, o0, 1);
                float p1 = __shfl_xor_sync(0xffffffffu, o1, 1);
                float p2 = __shfl_xor_sync(0xffffffffu, o2, 1);
                float p3 = __shfl_xor_sync(0xffffffffu, o3, 1);
                if (cp == 2) {
                    #pragma unroll
                    for (int half = 0; half < 2; half++) {
                        int rr = half ? r1 : r0;
                        float g0 = half ? o2 : o0;
                        float g1 = half ? o3 : o1;
                        float g2 = half ? p2 : p0;
                        float g3 = half ? p3 : p1;
                        if (rr < n) {
                            const float4* er = (const float4*)(ev + (size_t)rr * M_TOTAL);
                            float e[24];
                            #pragma unroll
                            for (int i = 0; i < 6; i++) {
                                float4 v = er[i];
                                e[4 * i] = v.x; e[4 * i + 1] = v.y;
                                e[4 * i + 2] = v.z; e[4 * i + 3] = v.w;
                            }
                            float o[24];
                            #pragma unroll
                            for (int mm = 0;  mm < 3;  mm++) o[mm] = g0 * e[mm];
                            #pragma unroll
                            for (int mm = 3;  mm < 8;  mm++) o[mm] = g1 * e[mm];
                            #pragma unroll
                            for (int mm = 8;  mm < 15; mm++) o[mm] = g2 * e[mm];
                            #pragma unroll
                            for (int mm = 15; mm < 24; mm++) o[mm] = g3 * e[mm];
                            float* od = out2base + (size_t)rr * M_TOTAL;
                            #pragma unroll
                            for (int q = 0; q < 6; q++)
                                *(float4*)(od + q * 4) = make_float4(
                                    o[q * 4], o[q * 4 + 1], o[q * 4 + 2], o[q * 4 + 3]);
                        }
                    }
                }
            }
        }
    }
}

extern "C" void kernel_launch(void* const* d_in, const int* in_sizes, int n_in,
                              void* d_out, int out_size)
{
    const float* x  = (const float*)d_in[0];
    const float* ev = (const float*)d_in[1];
    const float* W  = (const float*)d_in[2];
    const float* b  = (const float*)d_in[3];
    float* out = (float*)d_out;

    const int n = in_sizes[0] / F_DIM;
    const int numTiles = (n + BM - 1) / BM;

    cudaFuncSetAttribute(exchange_mma2_kernel,
                         cudaFuncAttributeMaxDynamicSharedMemorySize, SM_TOTAL);

    int dev = 0;
    cudaGetDevice(&dev);
    int sms = 148;
    cudaDeviceGetAttribute(&sms, cudaDevAttrMultiProcessorCount, dev);
    int grid = numTiles < sms ? numTiles : sms;

    exchange_mma2_kernel<<<grid, NT, SM_TOTAL>>>(x, ev, W, b, out, n, numTiles);
}

// round 12
// speedup vs baseline: 1.3478x; 1.3478x over previous
#include <cuda_runtime.h>
#include <cuda_bf16.h>
#include <cstdint>

#define F_DIM   132
#define M_TOTAL 24
#define D_IN    136
#define BM      128
#define NT      256
#define KSB     272                 // 136 bf16 per row, 16B-aligned, conflict-free
#define B_ROWS  136
#define MCH     (16 * KSB)          // 4352

#define A_BYTES (BM * KSB)          // 34816 (per h/l buffer)
#define B_BYTES (B_ROWS * KSB)      // 36992 (per h/l buffer)
#define XS_STRIDE 544               // 136 floats
#define SM_BIAS 0
#define SM_AH   1024
#define SM_AL   (SM_AH + A_BYTES)   // 35840
#define SM_BH   (SM_AL + A_BYTES)   // 70656
#define SM_BL   (SM_BH + B_BYTES)   // 107648
#define SM_XS   (SM_BL + B_BYTES)   // 144640
#define SM_EVS  (SM_XS + BM * XS_STRIDE)  // 214272
#define SM_TOTAL (SM_EVS + BM * 96)       // 226560
#define ADELTA  (SM_AL - SM_AH)
#define BDELTA  (SM_BL - SM_BH)

typedef unsigned int u32;

__device__ __forceinline__ u32 smem_u32(const void* p) {
    u32 a;
    asm("{ .reg .u64 t; cvta.to.shared.u64 t, %1; cvt.u32.u64 %0, t; }"
        : "=r"(a) : "l"(p));
    return a;
}
__device__ __forceinline__ void cpa16(u32 dst, const void* src) {
    asm volatile("cp.async.cg.shared.global [%0], [%1], 16;" :: "r"(dst), "l"(src));
}
__device__ __forceinline__ void cpa_commit() {
    asm volatile("cp.async.commit_group;" ::: "memory");
}
__device__ __forceinline__ void cpa_wait0() {
    asm volatile("cp.async.wait_group 0;" ::: "memory");
}
__device__ __forceinline__ void ldmat4(u32* r, u32 addr) {
    asm volatile("ldmatrix.sync.aligned.m8n8.x4.shared.b16 {%0,%1,%2,%3}, [%4];"
        : "=r"(r[0]), "=r"(r[1]), "=r"(r[2]), "=r"(r[3]) : "r"(addr));
}
__device__ __forceinline__ void ldmat2(u32* r, u32 addr) {
    asm volatile("ldmatrix.sync.aligned.m8n8.x2.shared.b16 {%0,%1}, [%2];"
        : "=r"(r[0]), "=r"(r[1]) : "r"(addr));
}
__device__ __forceinline__ void ldmat1(u32* r, u32 addr) {
    asm volatile("ldmatrix.sync.aligned.m8n8.x1.shared.b16 {%0}, [%1];"
        : "=r"(r[0]) : "r"(addr));
}
__device__ __forceinline__ void mma_bf16(float* c, const u32* a, const u32* b) {
    asm volatile("mma.sync.aligned.m16n8k16.row.col.f32.bf16.bf16.f32 "
        "{%0,%1,%2,%3}, {%4,%5,%6,%7}, {%8,%9}, {%0,%1,%2,%3};"
        : "+f"(c[0]), "+f"(c[1]), "+f"(c[2]), "+f"(c[3])
        : "r"(a[0]), "r"(a[1]), "r"(a[2]), "r"(a[3]), "r"(b[0]), "r"(b[1]));
}
__device__ __forceinline__ void mma_bf16_k8(float* c, const u32* a, u32 b) {
    asm volatile("mma.sync.aligned.m16n8k8.row.col.f32.bf16.bf16.f32 "
        "{%0,%1,%2,%3}, {%4,%5}, {%6}, {%0,%1,%2,%3};"
        : "+f"(c[0]), "+f"(c[1]), "+f"(c[2]), "+f"(c[3])
        : "r"(a[0]), "r"(a[1]), "r"(b));
}
__device__ __forceinline__ void split2(float a, float b, u32& hi, u32& lo) {
    __nv_bfloat16 ha = __float2bfloat16(a);
    __nv_bfloat16 hb = __float2bfloat16(b);
    __nv_bfloat16 la = __float2bfloat16(a - __bfloat162float(ha));
    __nv_bfloat16 lb = __float2bfloat16(b - __bfloat162float(hb));
    hi = ((u32)__bfloat16_as_ushort(hb) << 16) | (u32)__bfloat16_as_ushort(ha);
    lo = ((u32)__bfloat16_as_ushort(lb) << 16) | (u32)__bfloat16_as_ushort(la);
}

__global__ __launch_bounds__(NT, 1)
void exchange_mma3_kernel(const float* __restrict__ x,
                          const float* __restrict__ ev,
                          const float* __restrict__ W,
                          const float* __restrict__ b,
                          float* __restrict__ out,
                          int n, int numTiles)
{
    extern __shared__ char smem[];
    const u32 sb = smem_u32(smem);
    const int tid  = threadIdx.x;
    const int lane = tid & 31;
    const int wid  = tid >> 5;
    float* bs = (float*)(smem + SM_BIAS);
    float* out2base = out + (size_t)n * F_DIM;

    // ---- one-time: bias + Bh/Bl = bf16 hi/lo of W^T (Bs[nn][kk] = W[kk][nn]) ----
    for (int i = tid; i < D_IN; i += NT)
        bs[i] = b[i];
    for (int idx = tid; idx < D_IN * D_IN; idx += NT) {
        int kk = idx / D_IN;
        int nn = idx % D_IN;
        float wv = W[idx];
        __nv_bfloat16 h = __float2bfloat16(wv);
        __nv_bfloat16 l = __float2bfloat16(wv - __bfloat162float(h));
        *(__nv_bfloat16*)(smem + SM_BH + nn * KSB + kk * 2) = h;
        *(__nv_bfloat16*)(smem + SM_BL + nn * KSB + kk * 2) = l;
    }

    // ---- per-lane fragment addresses ----
    const u32 aRow = (u32)((lane & 7) + ((lane >> 3) & 1) * 8);
    const u32 aK   = (u32)(((lane >> 4) & 1) * 16);
    const u32 aAddr  = sb + SM_AH + (wid * 16 + aRow) * KSB + aK;
    const u32 aAddr8 = sb + SM_AH + (wid * 16 + (lane & 15)) * KSB + 256;
    const u32 bRow = (u32)((lane & 7) + ((lane >> 4) & 1) * 8);
    const u32 bK   = (u32)(((lane >> 3) & 1) * 16);
    const u32 bAddr   = sb + SM_BH + bRow * KSB + bK;
    const u32 bAddr8  = sb + SM_BH + (lane & 15) * KSB + 256;
    const u32 bAddrE  = sb + SM_BH + (128 + (lane & 7)) * KSB + bK;
    const u32 bAddrE8 = sb + SM_BH + (128 + (lane & 7)) * KSB + 256;

    const int r = tid >> 1;     // convert row within tile
    const int h = tid & 1;      // convert half

    // ---- prologue: prefetch first tile's x+ev into staging ----
    {
        int t0 = blockIdx.x;
        if (t0 < numTiles) {
            int rowBase = t0 * BM;
            for (int i = tid; i < BM * 33; i += NT) {
                int rr = i / 33, c = i % 33;
                int row = rowBase + rr;
                if (row < n)
                    cpa16(sb + SM_XS + rr * XS_STRIDE + c * 16,
                          x + (size_t)row * F_DIM + c * 4);
            }
            for (int i = tid; i < BM * 6; i += NT) {
                int rr = i / 6, c = i % 6;
                int row = rowBase + rr;
                if (row < n)
                    cpa16(sb + SM_EVS + rr * 96 + c * 16,
                          ev + (size_t)row * M_TOTAL + c * 4);
            }
        }
        cpa_commit();
    }

    for (int tile = blockIdx.x; tile < numTiles; tile += gridDim.x) {
        const int rowBase = tile * BM;

        cpa_wait0();
        __syncthreads();   // staging ready for all; prev tile's compute done

        // ================= convert staging -> bf16 A bufs =================
        {
            const int row = rowBase + r;
            const bool valid = row < n;
            const float4* xs = (const float4*)(smem + SM_XS + r * XS_STRIDE);
            const float4 zf4 = make_float4(0.f, 0.f, 0.f, 0.f);
            float4 xr[17];
            float c0 = 0.f, c1 = 0.f, c2 = 0.f, c3 = 0.f;

            if (h == 0) {
                #pragma unroll
                for (int i = 0; i < 8; i++) {
                    xr[2 * i]     = valid ? xs[4 * i]     : zf4;
                    xr[2 * i + 1] = valid ? xs[4 * i + 1] : zf4;
                }
                xr[16] = valid ? xs[32] : zf4;
                if (valid) {
                    const float4* er = (const float4*)(smem + SM_EVS + r * 96);
                    float e[24];
                    #pragma unroll
                    for (int i = 0; i < 6; i++) {
                        float4 v = er[i];
                        e[4 * i] = v.x; e[4 * i + 1] = v.y;
                        e[4 * i + 2] = v.z; e[4 * i + 3] = v.w;
                    }
                    #pragma unroll
                    for (int m = 0;  m < 3;  m++) c0 += e[m] * e[m];
                    #pragma unroll
                    for (int m = 3;  m < 8;  m++) c1 += e[m] * e[m];
                    #pragma unroll
                    for (int m = 8;  m < 15; m++) c2 += e[m] * e[m];
                    #pragma unroll
                    for (int m = 15; m < 24; m++) c3 += e[m] * e[m];
                }
            } else {
                #pragma unroll
                for (int i = 0; i < 8; i++) {
                    xr[2 * i]     = valid ? xs[4 * i + 2] : zf4;
                    xr[2 * i + 1] = valid ? xs[4 * i + 3] : zf4;
                }
            }

            char* Ah = smem + SM_AH + r * KSB;
            char* Al = smem + SM_AL + r * KSB;
            #pragma unroll
            for (int i = 0; i < 8; i++) {
                int c = 2 * i + h;
                uint4 hi, lo;
                split2(xr[2 * i].x,     xr[2 * i].y,     hi.x, lo.x);
                split2(xr[2 * i].z,     xr[2 * i].w,     hi.y, lo.y);
                split2(xr[2 * i + 1].x, xr[2 * i + 1].y, hi.z, lo.z);
                split2(xr[2 * i + 1].z, xr[2 * i + 1].w, hi.w, lo.w);
                *(uint4*)(Ah + c * 16) = hi;
                *(uint4*)(Al + c * 16) = lo;
            }
            if (h == 0) {      // k128..135: x[128..131] + contr[132..135]
                uint4 hi, lo;
                split2(xr[16].x, xr[16].y, hi.x, lo.x);
                split2(xr[16].z, xr[16].w, hi.y, lo.y);
                split2(c0, c1, hi.z, lo.z);
                split2(c2, c3, hi.w, lo.w);
                *(uint4*)(Ah + 256) = hi;
                *(uint4*)(Al + 256) = lo;
            }
        }
        __syncthreads();   // A bufs ready; staging free

        // ================= prefetch NEXT tile (overlaps compute) =================
        {
            int next = tile + gridDim.x;
            if (next < numTiles) {
                int nb = next * BM;
                for (int i = tid; i < BM * 33; i += NT) {
                    int rr = i / 33, c = i % 33;
                    int row = nb + rr;
                    if (row < n)
                        cpa16(sb + SM_XS + rr * XS_STRIDE + c * 16,
                              x + (size_t)row * F_DIM + c * 4);
                }
                for (int i = tid; i < BM * 6; i += NT) {
                    int rr = i / 6, c = i % 6;
                    int row = nb + rr;
                    if (row < n)
                        cpa16(sb + SM_EVS + rr * 96 + c * 16,
                              ev + (size_t)row * M_TOTAL + c * 4);
                }
            }
            cpa_commit();
        }

        // ================= compute: m16 x n136 per warp =================
        float acc[17][4];
        #pragma unroll
        for (int nc = 0; nc < 17; nc++)
            #pragma unroll
            for (int q = 0; q < 4; q++)
                acc[nc][q] = 0.f;

        #pragma unroll 1
        for (int s = 0; s < 8; s++) {           // k16 steps
            u32 ah[4], al[4];
            ldmat4(ah, aAddr + (u32)(s * 32));
            ldmat4(al, aAddr + (u32)(s * 32) + ADELTA);
            #pragma unroll
            for (int j = 0; j < 8; j++) {       // n16 chunks (cols 0..127)
                u32 bh[4], bl[4];
                u32 ba = bAddr + (u32)(j * MCH + s * 32);
                ldmat4(bh, ba);
                ldmat4(bl, ba + BDELTA);
                mma_bf16(acc[2 * j],     ah, bh);
                mma_bf16(acc[2 * j + 1], ah, bh + 2);
                mma_bf16(acc[2 * j],     ah, bl);
                mma_bf16(acc[2 * j + 1], ah, bl + 2);
                mma_bf16(acc[2 * j],     al, bh);
                mma_bf16(acc[2 * j + 1], al, bh + 2);
            }
            {   // n8 chunk: cols 128..135
                u32 bh2[2], bl2[2];
                ldmat2(bh2, bAddrE + (u32)(s * 32));
                ldmat2(bl2, bAddrE + (u32)(s * 32) + BDELTA);
                mma_bf16(acc[16], ah, bh2);
                mma_bf16(acc[16], ah, bl2);
                mma_bf16(acc[16], al, bh2);
            }
        }
        {   // ---- k8 tail: k = 128..135 ----
            u32 a2h[2], a2l[2];
            ldmat2(a2h, aAddr8);
            ldmat2(a2l, aAddr8 + ADELTA);
            #pragma unroll
            for (int j = 0; j < 8; j++) {
                u32 b2h[2], b2l[2];
                u32 ba = bAddr8 + (u32)(j * MCH);
                ldmat2(b2h, ba);
                ldmat2(b2l, ba + BDELTA);
                #pragma unroll
                for (int hf = 0; hf < 2; hf++) {
                    mma_bf16_k8(acc[2 * j + hf], a2h, b2h[hf]);
                    mma_bf16_k8(acc[2 * j + hf], a2h, b2l[hf]);
                    mma_bf16_k8(acc[2 * j + hf], a2l, b2h[hf]);
                }
            }
            {
                u32 b1h[1], b1l[1];
                ldmat1(b1h, bAddrE8);
                ldmat1(b1l, bAddrE8 + BDELTA);
                mma_bf16_k8(acc[16], a2h, b1h[0]);
                mma_bf16_k8(acc[16], a2h, b1l[0]);
                mma_bf16_k8(acc[16], a2l, b1h[0]);
            }
        }

        // ================= epilogue: direct fragment stores =================
        const int r0 = rowBase + wid * 16 + (lane >> 2);
        const int r1 = r0 + 8;
        const int cp = lane & 3;

        #pragma unroll
        for (int nc = 0; nc < 17; nc++) {
            int col = nc * 8 + cp * 2;
            if (col < F_DIM) {
                float b0 = bs[col], b1 = bs[col + 1];
                if (r0 < n)
                    *(float2*)(out + (size_t)r0 * F_DIM + col) =
                        make_float2(acc[nc][0] + b0, acc[nc][1] + b1);
                if (r1 < n)
                    *(float2*)(out + (size_t)r1 * F_DIM + col) =
                        make_float2(acc[nc][2] + b0, acc[nc][3] + b1);
            }
        }

        // cols 132..135 gate ev -> out2 (fragment nc=16, cp in {2,3})
        {
            int col = 128 + cp * 2;
            float b0 = (cp >= 2) ? bs[col]     : 0.f;
            float b1 = (cp >= 2) ? bs[col + 1] : 0.f;
            float o0 = acc[16][0] + b0, o1 = acc[16][1] + b1;
            float o2 = acc[16][2] + b0, o3 = acc[16][3] + b1;
            float p0 = __shfl_xor_sync(0xffffffffu, o0, 1);
            float p1 = __shfl_xor_sync(0xffffffffu, o1, 1);
            float p2 = __shfl_xor_sync(0xffffffffu, o2, 1);
            float p3 = __shfl_xor_sync(0xffffffffu, o3, 1);
            if (cp == 2) {
                #pragma unroll
                for (int half = 0; half < 2; half++) {
                    int rr = half ? r1 : r0;
                    float g0 = half ? o2 : o0;
                    float g1 = half ? o3 : o1;
                    float g2 = half ? p2 : p0;
                    float g3 = half ? p3 : p1;
                    if (rr < n) {
                        const float4* er = (const float4*)(ev + (size_t)rr * M_TOTAL);
                        float e[24];
                        #pragma unroll
                        for (int i = 0; i < 6; i++) {
                            float4 v = er[i];
                            e[4 * i] = v.x; e[4 * i + 1] = v.y;
                            e[4 * i + 2] = v.z; e[4 * i + 3] = v.w;
                        }
                        float o[24];
                        #pragma unroll
                        for (int m = 0;  m < 3;  m++) o[m] = g0 * e[m];
                        #pragma unroll
                        for (int m = 3;  m < 8;  m++) o[m] = g1 * e[m];
                        #pragma unroll
                        for (int m = 8;  m < 15; m++) o[m] = g2 * e[m];
                        #pragma unroll
                        for (int m = 15; m < 24; m++) o[m] = g3 * e[m];
                        float* od = out2base + (size_t)rr * M_TOTAL;
                        #pragma unroll
                        for (int q = 0; q < 6; q++)
                            *(float4*)(od + q * 4) = make_float4(
                                o[q * 4], o[q * 4 + 1], o[q * 4 + 2], o[q * 4 + 3]);
                    }
                }
            }
        }
    }
}

extern "C" void kernel_launch(void* const* d_in, const int* in_sizes, int n_in,
                              void* d_out, int out_size)
{
    const float* x  = (const float*)d_in[0];
    const float* ev = (const float*)d_in[1];
    const float* W  = (const float*)d_in[2];
    const float* b  = (const float*)d_in[3];
    float* out = (float*)d_out;

    const int n = in_sizes[0] / F_DIM;
    const int numTiles = (n + BM - 1) / BM;

    cudaFuncSetAttribute(exchange_mma3_kernel,
                         cudaFuncAttributeMaxDynamicSharedMemorySize, SM_TOTAL);

    int dev = 0;
    cudaGetDevice(&dev);
    int sms = 148;
    cudaDeviceGetAttribute(&sms, cudaDevAttrMultiProcessorCount, dev);
    int grid = numTiles < sms ? numTiles : sms;

    exchange_mma3_kernel<<<grid, NT, SM_TOTAL>>>(x, ev, W, b, out, n, numTiles);
}